// round 15
// baseline (speedup 1.0000x reference)
#include <cuda_runtime.h>
#include <cuda_fp16.h>
#include <cuda_bf16.h>
#include <math.h>
#include <stdint.h>

// Problem constants (fixed shapes)
#define Nn 10000
#define ROWP 10048          // Nn padded to 64
#define Ee 320000
#define Hh 128
#define H2 256
#define Lh 4
#define NG 64
#define NC 10
#define MSG_EPS 1e-7f

// ---------------- scratch (device globals; no allocation allowed) ----------------
__device__ float g_h[Nn * Hh];          // residual stream (fp32)
__device__ float g_r[Nn * Hh];          // relu(LN(h)) fp32 (pool input)
__device__ __half2 g_xh[Nn * 64];       // fp16 copy of agg input features
__device__ unsigned short g_ximg[ROWP * 256];    // x bf16 hi/lo image  (K=128)
__device__ unsigned short g_uimg[ROWP * 256];    // u bf16 hi/lo image  (K=128)
__device__ float g_pooled[NG * Hh];
__device__ int   g_cnt[Nn];
__device__ int   g_rowptr[Nn + 1];
__device__ int   g_pos[Nn];
__device__ int   g_psrc[Ee];
__device__ __half2 g_eah[(size_t)Ee * 64];       // edge_attr fp16, CSR order
// bf16-split weight images: NCH chunks of [COLS][72] halves (col-major, padded)
__device__ unsigned short g_img_enc[6 * 128 * 72];
__device__ unsigned short g_img_w1[4 * 6 * 256 * 72];
__device__ unsigned short g_img_w2[4 * 12 * 128 * 72];

static __device__ __forceinline__ unsigned pack_bf16x2(__nv_bfloat16 lo, __nv_bfloat16 hi) {
    unsigned short a = __bfloat16_as_ushort(lo);
    unsigned short b = __bfloat16_as_ushort(hi);
    return (unsigned)a | ((unsigned)b << 16);
}
static __device__ __forceinline__ unsigned h2u(__half2 v) {
    return *reinterpret_cast<unsigned*>(&v);
}
static __device__ __forceinline__ void store_hilo4(unsigned short* ph, unsigned short* pl,
                                                   float4 v) {
    __nv_bfloat16 h0 = __float2bfloat16_rn(v.x), h1 = __float2bfloat16_rn(v.y);
    __nv_bfloat16 h2 = __float2bfloat16_rn(v.z), h3 = __float2bfloat16_rn(v.w);
    __nv_bfloat16 l0 = __float2bfloat16_rn(v.x - __bfloat162float(h0));
    __nv_bfloat16 l1 = __float2bfloat16_rn(v.y - __bfloat162float(h1));
    __nv_bfloat16 l2 = __float2bfloat16_rn(v.z - __bfloat162float(h2));
    __nv_bfloat16 l3 = __float2bfloat16_rn(v.w - __bfloat162float(h3));
    *reinterpret_cast<uint2*>(ph) = make_uint2(pack_bf16x2(h0, h1), pack_bf16x2(h2, h3));
    *reinterpret_cast<uint2*>(pl) = make_uint2(pack_bf16x2(l0, l1), pack_bf16x2(l2, l3));
}
static __device__ __forceinline__ uint32_t smem_u32(const void* p) {
    uint32_t a;
    asm("{ .reg .u64 t; cvta.to.shared.u64 t, %1; cvt.u32.u64 %0, t; }" : "=r"(a) : "l"(p));
    return a;
}
static __device__ __forceinline__ void cp_async16(uint32_t sdst, const void* gsrc) {
    asm volatile("cp.async.cg.shared.global [%0], [%1], 16;" :: "r"(sdst), "l"(gsrc) : "memory");
}
#define CP_COMMIT() asm volatile("cp.async.commit_group;" ::: "memory")
#define CP_WAIT0() asm volatile("cp.async.wait_group 0;" ::: "memory")
static __device__ __forceinline__ void ldsm_x4(unsigned& a0, unsigned& a1, unsigned& a2,
                                               unsigned& a3, uint32_t addr) {
    asm volatile("ldmatrix.sync.aligned.m8n8.x4.shared.b16 {%0,%1,%2,%3}, [%4];"
                 : "=r"(a0), "=r"(a1), "=r"(a2), "=r"(a3) : "r"(addr));
}
#define MMA16816(acc, a0, a1, a2, a3, b0, b1) \
    asm volatile( \
        "mma.sync.aligned.m16n8k16.row.col.f32.bf16.bf16.f32 " \
        "{%0,%1,%2,%3}, {%4,%5,%6,%7}, {%8,%9}, {%0,%1,%2,%3};" \
        : "+f"((acc)[0]), "+f"((acc)[1]), "+f"((acc)[2]), "+f"((acc)[3]) \
        : "r"(a0), "r"(a1), "r"(a2), "r"(a3), "r"(b0), "r"(b1))

// ---------------- small utility kernels ----------------
__global__ void fill_i32(int* p, int v, int n) {
    int i = blockIdx.x * blockDim.x + threadIdx.x;
    if (i < n) p[i] = v;
}
__global__ void fill_f32(float* p, float v, int n) {
    int i = blockIdx.x * blockDim.x + threadIdx.x;
    if (i < n) p[i] = v;
}

// x fp32 -> bf16 hi/lo image (K=128), zero-pad rows >= Nn
__global__ void conv_a_kernel(const float* __restrict__ src, unsigned short* __restrict__ img) {
    int idx = blockIdx.x * blockDim.x + threadIdx.x;
    if (idx >= ROWP * 128) return;
    int row = idx >> 7, k = idx & 127;
    float v = (row < Nn) ? __ldg(&src[(size_t)row * 128 + k]) : 0.f;
    __nv_bfloat16 h = __float2bfloat16_rn(v);
    __nv_bfloat16 l = __float2bfloat16_rn(v - __bfloat162float(h));
    img[(size_t)row * 256 + k] = __bfloat16_as_ushort(h);
    img[(size_t)row * 256 + 128 + k] = __bfloat16_as_ushort(l);
}

// ---------------- CSR build ----------------
__global__ void hist_kernel(const int* __restrict__ dst, int* cnt) {
    int e = blockIdx.x * blockDim.x + threadIdx.x;
    if (e < Ee) atomicAdd(&cnt[dst[e]], 1);
}

__global__ __launch_bounds__(1024) void scan_kernel(const int* __restrict__ cnt,
                                                    int* rowptr, int* pos) {
    __shared__ int part[1024];
    const int CH = 10;
    int tid = threadIdx.x;
    int base = tid * CH;
    int loc[CH];
    int s = 0;
#pragma unroll
    for (int i = 0; i < CH; i++) {
        int idx = base + i;
        int v = (idx < Nn) ? cnt[idx] : 0;
        loc[i] = s;
        s += v;
    }
    part[tid] = s;
    __syncthreads();
    for (int off = 1; off < 1024; off <<= 1) {
        int v = (tid >= off) ? part[tid - off] : 0;
        __syncthreads();
        part[tid] += v;
        __syncthreads();
    }
    int pre = (tid > 0) ? part[tid - 1] : 0;
#pragma unroll
    for (int i = 0; i < CH; i++) {
        int idx = base + i;
        int v = pre + loc[i];
        if (idx <= Nn) rowptr[idx] = v;
        if (idx < Nn) pos[idx] = v;
    }
}

// fused scatter + edge_attr fp16 reorder (warp per edge)
__global__ void scat_ea_kernel(const int* __restrict__ src, const int* __restrict__ dst,
                               const float* __restrict__ ea, int* pos,
                               int* __restrict__ psrc, __half2* __restrict__ eah) {
    int j = (blockIdx.x * blockDim.x + threadIdx.x) >> 5;
    if (j >= Ee) return;
    int lane = threadIdx.x & 31;
    int slot = 0;
    if (lane == 0) {
        int d = __ldg(&dst[j]);
        slot = atomicAdd(&pos[d], 1);
        psrc[slot] = __ldg(&src[j]);
    }
    slot = __shfl_sync(0xffffffffu, slot, 0);
    float4 v = __ldg(reinterpret_cast<const float4*>(ea + (size_t)j * Hh) + lane);
    eah[(size_t)slot * 64 + lane * 2]     = __floats2half2_rn(v.x, v.y);
    eah[(size_t)slot * 64 + lane * 2 + 1] = __floats2half2_rn(v.z, v.w);
}

// ---------------- weight image prep ----------------
__global__ void conv_w_kernel(const float* __restrict__ Wsrc, unsigned short* __restrict__ img,
                              int K, int COLS, int lstride, int imgstride) {
    int layer = blockIdx.y;
    const float* W = Wsrc + (size_t)layer * lstride;
    unsigned short* out = img + (size_t)layer * imgstride;
    int total = (3 * K / 64) * COLS * 64;
    for (int idx = blockIdx.x * blockDim.x + threadIdx.x; idx < total;
         idx += gridDim.x * blockDim.x) {
        int c = idx / (COLS * 64);
        int rem = idx % (COLS * 64);
        int n = rem / 64, kc = rem % 64;
        int kp = c * 64 + kc;
        int sec_lo = (kp >= K && kp < 2 * K);
        int kg = kp;
        if (kg >= 2 * K) kg -= 2 * K;
        else if (kg >= K) kg -= K;
        float w = __ldg(&W[(size_t)kg * COLS + n]);
        __nv_bfloat16 h = __float2bfloat16_rn(w);
        if (sec_lo) h = __float2bfloat16_rn(w - __bfloat162float(h));
        out[(size_t)c * COLS * 72 + n * 72 + kc] = __bfloat16_as_ushort(h);
    }
}

// ---------------- aggregation (fp16 x, writes u bf16 hi/lo image) ----------------
__global__ void agg_kernel(const __half2* __restrict__ xh, const __half2* __restrict__ eah,
                           const int* __restrict__ rowptr, const int* __restrict__ psrc,
                           const float* __restrict__ tp, int layer,
                           unsigned short* __restrict__ uimg) {
    int w = (blockIdx.x * blockDim.x + threadIdx.x) >> 5;
    if (w >= Nn) return;
    int lane = threadIdx.x & 31;
    float t = tp[layer];
    int beg = rowptr[w], end = rowptr[w + 1];
    float Sx = 0.f, Sy = 0.f, Sz = 0.f, Sw = 0.f;
    float Ax = 0.f, Ay = 0.f, Az = 0.f, Aw = 0.f;
#pragma unroll 4
    for (int j = beg; j < end; j++) {
        int s = __ldg(&psrc[j]);
        uint2 eu = __ldg(reinterpret_cast<const uint2*>(eah + (size_t)j * 64) + lane);
        uint2 xu = __ldg(reinterpret_cast<const uint2*>(xh + (size_t)s * 64) + lane);
        float2 e01 = __half22float2(*reinterpret_cast<__half2*>(&eu.x));
        float2 e23 = __half22float2(*reinterpret_cast<__half2*>(&eu.y));
        float2 x01 = __half22float2(*reinterpret_cast<__half2*>(&xu.x));
        float2 x23 = __half22float2(*reinterpret_cast<__half2*>(&xu.y));
        float mx = fmaxf(x01.x + e01.x, 0.f) + MSG_EPS;
        float my = fmaxf(x01.y + e01.y, 0.f) + MSG_EPS;
        float mz = fmaxf(x23.x + e23.x, 0.f) + MSG_EPS;
        float mw = fmaxf(x23.y + e23.y, 0.f) + MSG_EPS;
        float exx = __expf(mx * t), exy = __expf(my * t);
        float exz = __expf(mz * t), exw = __expf(mw * t);
        Sx += exx; Sy += exy; Sz += exz; Sw += exw;
        Ax = fmaf(mx, exx, Ax); Ay = fmaf(my, exy, Ay);
        Az = fmaf(mz, exz, Az); Aw = fmaf(mw, exw, Aw);
    }
    uint2 xnu = *(reinterpret_cast<const uint2*>(xh + (size_t)w * 64) + lane);
    float2 xn01 = __half22float2(*reinterpret_cast<__half2*>(&xnu.x));
    float2 xn23 = __half22float2(*reinterpret_cast<__half2*>(&xnu.y));
    float4 o;
    if (end > beg) {
        o.x = Ax / Sx + xn01.x;
        o.y = Ay / Sy + xn01.y;
        o.z = Az / Sz + xn23.x;
        o.w = Aw / Sw + xn23.y;
    } else {
        o = make_float4(xn01.x, xn01.y, xn23.x, xn23.y);
    }
    unsigned short* bh = uimg + (size_t)w * 256 + lane * 4;
    store_hilo4(bh, bh + 128, o);
}

// ================= encoder GEMM (32-row tiles) — unchanged from R12 EPI0 ========
__global__ __launch_bounds__(256, 3) void gemm_enc(const unsigned short* __restrict__ Aimg,
                                                   const unsigned short* __restrict__ img,
                                                   const float* __restrict__ bias,
                                                   float* __restrict__ C,
                                                   __half2* __restrict__ Yh, int nrows) {
    constexpr int K = 128, COLS = 128;
    constexpr int SA = K + 8;
    constexpr int NCH = 6;
    constexpr int WB = COLS * 72;
    constexpr int NT = COLS / 32;
    constexpr int CS = COLS + 4;
    constexpr int CPR = K / 8;

    extern __shared__ __align__(16) unsigned short smem_us[];
    unsigned short* sAhi = smem_us;
    unsigned short* sAlo = smem_us + 32 * SA;
    unsigned short* sW = smem_us + 64 * SA;
    float* Cbuf = reinterpret_cast<float*>(smem_us);

    int tid = threadIdx.x, wid = tid >> 5, lane = tid & 31;
    int g = lane >> 2, tg = lane & 3;
    int wm = wid & 1, wn = wid >> 1;
    int row0 = blockIdx.x * 32;
    uint32_t sWU = smem_u32(sW);
    uint32_t aU_hi = smem_u32(sAhi);
    uint32_t aU_lo = smem_u32(sAlo);

    {
        const char* base = reinterpret_cast<const char*>(Aimg) + (size_t)row0 * 4 * K;
        for (int i = tid; i < 64 * CPR; i += 256) {
            int piece = i / CPR, off = i % CPR;
            int r = piece >> 1, hl = piece & 1;
            uint32_t dst = (hl ? aU_lo : aU_hi) + (uint32_t)(r * SA * 2 + off * 16);
            cp_async16(dst, base + (size_t)r * 4 * K + hl * 2 * K + off * 16);
        }
    }
    {
        const char* srcb = reinterpret_cast<const char*>(img);
        for (int i = tid; i < COLS * 9; i += 256)
            cp_async16(sWU + (uint32_t)i * 16, srcb + (size_t)i * 16);
        CP_COMMIT();
    }

    float acc[NT][4];
#pragma unroll
    for (int j = 0; j < NT; j++)
#pragma unroll
        for (int q = 0; q < 4; q++) acc[j][q] = 0.f;

    int rowA = wm * 16 + (lane & 15);
    int colsel = (lane >> 4) << 3;

    for (int c = 0; c < NCH; c++) {
        CP_WAIT0();
        __syncthreads();
        if (c + 1 < NCH) {
            uint32_t dstb = sWU + (uint32_t)(((c + 1) & 1) * WB * 2);
            const char* srcb = reinterpret_cast<const char*>(img) + (size_t)(c + 1) * WB * 2;
            for (int i = tid; i < COLS * 9; i += 256)
                cp_async16(dstb + (uint32_t)i * 16, srcb + (size_t)i * 16);
            CP_COMMIT();
        }
        int kp = c * 64;
        uint32_t aU = (kp < 2 * K) ? aU_hi : aU_lo;
        int koffA = kp;
        if (koffA >= 2 * K) koffA -= 2 * K;
        else if (koffA >= K) koffA -= K;
        const unsigned short* sWb = sW + (c & 1) * WB;
#pragma unroll
        for (int ks = 0; ks < 4; ks++) {
            int kw = ks * 16 + tg * 2;
            unsigned bf0[NT], bf1[NT];
#pragma unroll
            for (int j = 0; j < NT; j++) {
                int n = wn * (COLS / 4) + j * 8 + g;
                bf0[j] = *reinterpret_cast<const unsigned*>(sWb + n * 72 + kw);
                bf1[j] = *reinterpret_cast<const unsigned*>(sWb + n * 72 + kw + 8);
            }
            unsigned a0, a1, a2, a3;
            ldsm_x4(a0, a1, a2, a3,
                    aU + (uint32_t)((rowA * SA + koffA + ks * 16 + colsel) * 2));
#pragma unroll
            for (int j = 0; j < NT; j++) MMA16816(acc[j], a0, a1, a2, a3, bf0[j], bf1[j]);
        }
        __syncthreads();
    }

    {
        int r = wm * 16 + g;
#pragma unroll
        for (int j = 0; j < NT; j++) {
            int ncol = wn * (COLS / 4) + j * 8 + tg * 2;
            *reinterpret_cast<float2*>(Cbuf + r * CS + ncol) = make_float2(acc[j][0], acc[j][1]);
            *reinterpret_cast<float2*>(Cbuf + (r + 8) * CS + ncol) =
                make_float2(acc[j][2], acc[j][3]);
        }
    }
    __syncthreads();

    float4 b4 = __ldg(reinterpret_cast<const float4*>(bias) + lane);
    for (int rr = 0; rr < 4; rr++) {
        int r = wid * 4 + rr;
        int row = row0 + r;
        if (row >= nrows) break;
        float4 h = reinterpret_cast<const float4*>(Cbuf + r * CS)[lane];
        h.x += b4.x; h.y += b4.y; h.z += b4.z; h.w += b4.w;
        reinterpret_cast<float4*>(C + (size_t)row * 128)[lane] = h;
        reinterpret_cast<uint2*>(Yh + (size_t)row * 64)[lane] = make_uint2(
            h2u(__floats2half2_rn(h.x, h.y)), h2u(__floats2half2_rn(h.z, h.w)));
    }
}

// ================= fused layer kernel: hid = relu(LN256(u@W1+b1)) in smem;
//                   h (+)= hid@W2+b2; y = relu(LN128(h)) -> C/Yf/Yh ==============
// smem layout (ushort units):
//  A1: 0..8704 (32x136 hi + 32x136 lo)        [phase 1]
//  W1: 8704..45568 (2 x 256*72)               [phase 1]
//  A2: 0..16896 (2 x 32x264 hi/lo)            [written in epi-1, read phase 2]
//  W2 region P: 16896..26112 (128*72)         [phase 2, odd chunks]
//  W2 region F: 45568..54784 (128*72)         [phase 2, even chunks]
//  Cbuf2 (fp32 32x132): offset 0              [epi-2, after phase 2]
template <bool ACC>
__global__ __launch_bounds__(256, 2) void gemm_layer(
    const unsigned short* __restrict__ Aimg, const unsigned short* __restrict__ img1,
    const unsigned short* __restrict__ img2, const float* __restrict__ b1,
    const float* __restrict__ mgp, const float* __restrict__ mbp,
    const float* __restrict__ b2, const float* __restrict__ lgp,
    const float* __restrict__ lbp, float* __restrict__ C, float* __restrict__ Yf,
    __half2* __restrict__ Yh, int nrows) {
    constexpr int K1 = 128, C1 = 256, SA1 = 136, NCH1 = 6, WB1 = 256 * 72;
    constexpr int K2 = 256, C2 = 128, SA2 = 264, NCH2 = 12, WB2 = 128 * 72;
    constexpr int NT1 = 8, NT2 = 4;
    constexpr int OFF_W1 = 8704, OFF_A2 = 0, OFF_P = 16896, OFF_F = 45568;
    constexpr int CS2 = C2 + 4;

    extern __shared__ __align__(16) unsigned short smem_us[];
    __shared__ float red[32][4][2];

    int tid = threadIdx.x, wid = tid >> 5, lane = tid & 31;
    int g = lane >> 2, tg = lane & 3;
    int wm = wid & 1, wn = wid >> 1;
    int row0 = blockIdx.x * 32;
    uint32_t base = smem_u32(smem_us);
    uint32_t a1hi = base, a1lo = base + 32 * SA1 * 2;
    uint32_t w1U = base + OFF_W1 * 2;
    uint32_t a2hi = base + OFF_A2 * 2, a2lo = a2hi + 32 * SA2 * 2;
    uint32_t pU = base + OFF_P * 2, fU = base + OFF_F * 2;

    // ---- A1 (u image) + W1 c0 + W2 c0 (-> F) ----
    {
        const char* ab = reinterpret_cast<const char*>(Aimg) + (size_t)row0 * 4 * K1;
        for (int i = tid; i < 64 * 16; i += 256) {
            int piece = i / 16, off = i % 16;
            int r = piece >> 1, hl = piece & 1;
            uint32_t dst = (hl ? a1lo : a1hi) + (uint32_t)(r * SA1 * 2 + off * 16);
            cp_async16(dst, ab + (size_t)r * 4 * K1 + hl * 2 * K1 + off * 16);
        }
        const char* w1b = reinterpret_cast<const char*>(img1);
        for (int i = tid; i < C1 * 9; i += 256)
            cp_async16(w1U + (uint32_t)i * 16, w1b + (size_t)i * 16);
        const char* w2b = reinterpret_cast<const char*>(img2);
        for (int i = tid; i < C2 * 9; i += 256)
            cp_async16(fU + (uint32_t)i * 16, w2b + (size_t)i * 16);
        CP_COMMIT();
    }

    float acc[NT1][4];
#pragma unroll
    for (int j = 0; j < NT1; j++)
#pragma unroll
        for (int q = 0; q < 4; q++) acc[j][q] = 0.f;

    int rowA = wm * 16 + (lane & 15);
    int colsel = (lane >> 4) << 3;

    // ================= phase 1: u @ W1 =================
    for (int c = 0; c < NCH1; c++) {
        CP_WAIT0();
        __syncthreads();
        if (c + 1 < NCH1) {
            uint32_t dstb = w1U + (uint32_t)(((c + 1) & 1) * WB1 * 2);
            const char* srcb = reinterpret_cast<const char*>(img1) + (size_t)(c + 1) * WB1 * 2;
            for (int i = tid; i < C1 * 9; i += 256)
                cp_async16(dstb + (uint32_t)i * 16, srcb + (size_t)i * 16);
            CP_COMMIT();
        }
        int kp = c * 64;
        uint32_t aU = (kp < 2 * K1) ? a1hi : a1lo;
        int koffA = kp;
        if (koffA >= 2 * K1) koffA -= 2 * K1;
        else if (koffA >= K1) koffA -= K1;
        const unsigned short* sWb = smem_us + OFF_W1 + (c & 1) * WB1;
#pragma unroll
        for (int ks = 0; ks < 4; ks++) {
            int kw = ks * 16 + tg * 2;
            unsigned bf0[NT1], bf1[NT1];
#pragma unroll
            for (int j = 0; j < NT1; j++) {
                int n = wn * (C1 / 4) + j * 8 + g;
                bf0[j] = *reinterpret_cast<const unsigned*>(sWb + n * 72 + kw);
                bf1[j] = *reinterpret_cast<const unsigned*>(sWb + n * 72 + kw + 8);
            }
            unsigned a0, a1, a2, a3;
            ldsm_x4(a0, a1, a2, a3,
                    aU + (uint32_t)((rowA * SA1 + koffA + ks * 16 + colsel) * 2));
#pragma unroll
            for (int j = 0; j < NT1; j++) MMA16816(acc[j], a0, a1, a2, a3, bf0[j], bf1[j]);
        }
        __syncthreads();
    }
    // A1/W1 regions now dead. Prefetch W2 c1 -> P during epilogue.
    {
        const char* w2b = reinterpret_cast<const char*>(img2) + (size_t)WB2 * 2;
        for (int i = tid; i < C2 * 9; i += 256)
            cp_async16(pU + (uint32_t)i * 16, w2b + (size_t)i * 16);
        CP_COMMIT();
    }

    // ================= epilogue 1: bias + LN256 + ReLU -> A2 (bf16 hi/lo) ========
    {
        int r1 = wm * 16 + g, r2 = r1 + 8;
        float s1 = 0.f, q1 = 0.f, s2 = 0.f, q2 = 0.f;
#pragma unroll
        for (int j = 0; j < NT1; j++) {
            int cc = wn * 64 + j * 8 + tg * 2;
            float2 bb = *reinterpret_cast<const float2*>(b1 + cc);
            acc[j][0] += bb.x; acc[j][1] += bb.y;
            acc[j][2] += bb.x; acc[j][3] += bb.y;
            s1 += acc[j][0] + acc[j][1];
            q1 += acc[j][0] * acc[j][0] + acc[j][1] * acc[j][1];
            s2 += acc[j][2] + acc[j][3];
            q2 += acc[j][2] * acc[j][2] + acc[j][3] * acc[j][3];
        }
#pragma unroll
        for (int o = 1; o <= 2; o <<= 1) {
            s1 += __shfl_xor_sync(0xffffffffu, s1, o);
            q1 += __shfl_xor_sync(0xffffffffu, q1, o);
            s2 += __shfl_xor_sync(0xffffffffu, s2, o);
            q2 += __shfl_xor_sync(0xffffffffu, q2, o);
        }
        if (tg == 0) {
            red[r1][wn][0] = s1; red[r1][wn][1] = q1;
            red[r2][wn][0] = s2; red[r2][wn][1] = q2;
        }
        __syncthreads();
        float ts1 = red[r1][0][0] + red[r1][1][0] + red[r1][2][0] + red[r1][3][0];
        float tq1 = red[r1][0][1] + red[r1][1][1] + red[r1][2][1] + red[r1][3][1];
        float ts2 = red[r2][0][0] + red[r2][1][0] + red[r2][2][0] + red[r2][3][0];
        float tq2 = red[r2][0][1] + red[r2][1][1] + red[r2][2][1] + red[r2][3][1];
        float mu1 = ts1 * (1.f / 256.f);
        float inv1 = rsqrtf(tq1 * (1.f / 256.f) - mu1 * mu1 + 1e-5f);
        float mu2 = ts2 * (1.f / 256.f);
        float inv2 = rsqrtf(tq2 * (1.f / 256.f) - mu2 * mu2 + 1e-5f);
        __syncthreads();  // A1/W1 reads fully done; A2 region safe to write
#pragma unroll
        for (int j = 0; j < NT1; j++) {
            int cc = wn * 64 + j * 8 + tg * 2;
            float2 gg = *reinterpret_cast<const float2*>(mgp + cc);
            float2 bb = *reinterpret_cast<const float2*>(mbp + cc);
            float y0 = fmaxf((acc[j][0] - mu1) * inv1 * gg.x + bb.x, 0.f);
            float y1 = fmaxf((acc[j][1] - mu1) * inv1 * gg.y + bb.y, 0.f);
            float y2 = fmaxf((acc[j][2] - mu2) * inv2 * gg.x + bb.x, 0.f);
            float y3 = fmaxf((acc[j][3] - mu2) * inv2 * gg.y + bb.y, 0.f);
            __nv_bfloat16 h0 = __float2bfloat16_rn(y0), h1 = __float2bfloat16_rn(y1);
            __nv_bfloat16 h2 = __float2bfloat16_rn(y2), h3 = __float2bfloat16_rn(y3);
            __nv_bfloat16 l0 = __float2bfloat16_rn(y0 - __bfloat162float(h0));
            __nv_bfloat16 l1 = __float2bfloat16_rn(y1 - __bfloat162float(h1));
            __nv_bfloat16 l2 = __float2bfloat16_rn(y2 - __bfloat162float(h2));
            __nv_bfloat16 l3 = __float2bfloat16_rn(y3 - __bfloat162float(h3));
            *reinterpret_cast<unsigned*>(smem_us + OFF_A2 + r1 * SA2 + cc) = pack_bf16x2(h0, h1);
            *reinterpret_cast<unsigned*>(smem_us + OFF_A2 + r2 * SA2 + cc) = pack_bf16x2(h2, h3);
            *reinterpret_cast<unsigned*>(smem_us + OFF_A2 + 32 * SA2 + r1 * SA2 + cc) =
                pack_bf16x2(l0, l1);
            *reinterpret_cast<unsigned*>(smem_us + OFF_A2 + 32 * SA2 + r2 * SA2 + cc) =
                pack_bf16x2(l2, l3);
        }
    }
    __syncthreads();

    // ================= phase 2: hid @ W2 =================
    float acc2[NT2][4];
#pragma unroll
    for (int j = 0; j < NT2; j++)
#pragma unroll
        for (int q = 0; q < 4; q++) acc2[j][q] = 0.f;

    for (int c = 0; c < NCH2; c++) {
        CP_WAIT0();
        __syncthreads();
        if (c >= 1 && c + 1 < NCH2) {
            uint32_t dstb = ((c + 1) & 1) ? pU : fU;
            const char* srcb = reinterpret_cast<const char*>(img2) + (size_t)(c + 1) * WB2 * 2;
            for (int i = tid; i < C2 * 9; i += 256)
                cp_async16(dstb + (uint32_t)i * 16, srcb + (size_t)i * 16);
            CP_COMMIT();
        }
        int kp = c * 64;
        uint32_t aU = (kp < 2 * K2) ? a2hi : a2lo;
        int koffA = kp;
        if (koffA >= 2 * K2) koffA -= 2 * K2;
        else if (koffA >= K2) koffA -= K2;
        const unsigned short* sWb = smem_us + ((c & 1) ? OFF_P : OFF_F);
#pragma unroll
        for (int ks = 0; ks < 4; ks++) {
            int kw = ks * 16 + tg * 2;
            unsigned bf0[NT2], bf1[NT2];
#pragma unroll
            for (int j = 0; j < NT2; j++) {
                int n = wn * (C2 / 4) + j * 8 + g;
                bf0[j] = *reinterpret_cast<const unsigned*>(sWb + n * 72 + kw);
                bf1[j] = *reinterpret_cast<const unsigned*>(sWb + n * 72 + kw + 8);
            }
            unsigned a0, a1, a2, a3;
            ldsm_x4(a0, a1, a2, a3,
                    aU + (uint32_t)((rowA * SA2 + koffA + ks * 16 + colsel) * 2));
#pragma unroll
            for (int j = 0; j < NT2; j++) MMA16816(acc2[j], a0, a1, a2, a3, bf0[j], bf1[j]);
        }
        __syncthreads();
    }

    // ================= epilogue 2: residual + LN128 -> C/Yf/Yh =================
    float* Cbuf = reinterpret_cast<float*>(smem_us);
    {
        int r = wm * 16 + g;
#pragma unroll
        for (int j = 0; j < NT2; j++) {
            int ncol = wn * (C2 / 4) + j * 8 + tg * 2;
            *reinterpret_cast<float2*>(Cbuf + r * CS2 + ncol) = make_float2(acc2[j][0], acc2[j][1]);
            *reinterpret_cast<float2*>(Cbuf + (r + 8) * CS2 + ncol) =
                make_float2(acc2[j][2], acc2[j][3]);
        }
    }
    __syncthreads();

    float4 b4 = __ldg(reinterpret_cast<const float4*>(b2) + lane);
    float4 gv = __ldg(reinterpret_cast<const float4*>(lgp) + lane);
    float4 bv = __ldg(reinterpret_cast<const float4*>(lbp) + lane);
    for (int rr = 0; rr < 4; rr++) {
        int r = wid * 4 + rr;
        int row = row0 + r;
        if (row >= nrows) break;
        float4 h = reinterpret_cast<const float4*>(Cbuf + r * CS2)[lane];
        h.x += b4.x; h.y += b4.y; h.z += b4.z; h.w += b4.w;
        if (ACC) {
            float4 old = __ldg(reinterpret_cast<const float4*>(C + (size_t)row * 128) + lane);
            h.x += old.x; h.y += old.y; h.z += old.z; h.w += old.w;
        }
        float s = h.x + h.y + h.z + h.w;
        float s2 = h.x * h.x + h.y * h.y + h.z * h.z + h.w * h.w;
#pragma unroll
        for (int o = 16; o > 0; o >>= 1) {
            s += __shfl_xor_sync(0xffffffffu, s, o);
            s2 += __shfl_xor_sync(0xffffffffu, s2, o);
        }
        float mu = s * (1.f / 128.f);
        float var = s2 * (1.f / 128.f) - mu * mu;
        float inv = rsqrtf(var + 1e-5f);
        float4 y;
        y.x = fmaxf((h.x - mu) * inv * gv.x + bv.x, 0.f);
        y.y = fmaxf((h.y - mu) * inv * gv.y + bv.y, 0.f);
        y.z = fmaxf((h.z - mu) * inv * gv.z + bv.z, 0.f);
        y.w = fmaxf((h.w - mu) * inv * gv.w + bv.w, 0.f);
        reinterpret_cast<float4*>(C + (size_t)row * 128)[lane] = h;
        reinterpret_cast<float4*>(Yf + (size_t)row * 128)[lane] = y;
        reinterpret_cast<uint2*>(Yh + (size_t)row * 64)[lane] = make_uint2(
            h2u(__floats2half2_rn(y.x, y.y)), h2u(__floats2half2_rn(y.z, y.w)));
    }
}

// ---------------- global_add_pool ----------------
__global__ void pool_kernel(const float* __restrict__ r, const int* __restrict__ batch,
                            float* pooled) {
    int w = (blockIdx.x * blockDim.x + threadIdx.x) >> 5;
    if (w >= Nn) return;
    int lane = threadIdx.x & 31;
    int gidx = batch[w];
    float4 v = *(reinterpret_cast<const float4*>(r + (size_t)w * Hh) + lane);
    float* dp = pooled + gidx * Hh + lane * 4;
    atomicAdd(dp + 0, v.x);
    atomicAdd(dp + 1, v.y);
    atomicAdd(dp + 2, v.z);
    atomicAdd(dp + 3, v.w);
}

// ---------------- classifier + output assembly ----------------
__global__ void final_kernel(const float* __restrict__ pooled, const float* __restrict__ linW,
                             const float* __restrict__ linb, float* __restrict__ out) {
    int idx = blockIdx.x * blockDim.x + threadIdx.x;
    int total = blockDim.x * gridDim.x;
    if (idx < NG * NC) {
        int gi = idx / NC, c = idx % NC;
        float sum = linb[c];
#pragma unroll 8
        for (int k = 0; k < Hh; k++) sum = fmaf(pooled[gi * Hh + k], linW[k * NC + c], sum);
        out[idx] = sum;
    }
    for (int i = idx; i < NG * Hh; i += total) out[NG * NC + i] = pooled[i];
}

// ---------------- launch ----------------
extern "C" void kernel_launch(void* const* d_in, const int* in_sizes, int n_in,
                              void* d_out, int out_size) {
    const float* x    = (const float*)d_in[0];
    const float* ea   = (const float*)d_in[1];
    const float* encW = (const float*)d_in[2];
    const float* encB = (const float*)d_in[3];
    const float* tp   = (const float*)d_in[4];
    const float* W1   = (const float*)d_in[5];
    const float* b1   = (const float*)d_in[6];
    const float* mg   = (const float*)d_in[7];
    const float* mb   = (const float*)d_in[8];
    const float* W2   = (const float*)d_in[9];
    const float* b2   = (const float*)d_in[10];
    const float* lg   = (const float*)d_in[11];
    const float* lb   = (const float*)d_in[12];
    const float* linW = (const float*)d_in[13];
    const float* linB = (const float*)d_in[14];
    const int*   eidx = (const int*)d_in[15];
    const int*   batch= (const int*)d_in[16];
    float* out = (float*)d_out;

    float *ph, *pr, *ppool;
    int *pcnt, *prow, *ppos, *ppsrc;
    __half2 *peah, *pxh;
    unsigned short *pimg_enc, *pimg_w1, *pimg_w2, *pximg, *puimg;
    cudaGetSymbolAddress((void**)&ph, g_h);
    cudaGetSymbolAddress((void**)&pr, g_r);
    cudaGetSymbolAddress((void**)&pxh, g_xh);
    cudaGetSymbolAddress((void**)&pximg, g_ximg);
    cudaGetSymbolAddress((void**)&puimg, g_uimg);
    cudaGetSymbolAddress((void**)&ppool, g_pooled);
    cudaGetSymbolAddress((void**)&pcnt, g_cnt);
    cudaGetSymbolAddress((void**)&prow, g_rowptr);
    cudaGetSymbolAddress((void**)&ppos, g_pos);
    cudaGetSymbolAddress((void**)&ppsrc, g_psrc);
    cudaGetSymbolAddress((void**)&peah, g_eah);
    cudaGetSymbolAddress((void**)&pimg_enc, g_img_enc);
    cudaGetSymbolAddress((void**)&pimg_w1, g_img_w1);
    cudaGetSymbolAddress((void**)&pimg_w2, g_img_w2);

    const int smem_enc = (64 * 136 + 2 * 128 * 72) * 2;   // 54272
    const int smem_lay = 54784 * 2;                       // 109568
    cudaFuncSetAttribute((const void*)gemm_enc,
                         cudaFuncAttributeMaxDynamicSharedMemorySize, smem_enc);
    cudaFuncSetAttribute((const void*)gemm_layer<false>,
                         cudaFuncAttributeMaxDynamicSharedMemorySize, smem_lay);
    cudaFuncSetAttribute((const void*)gemm_layer<true>,
                         cudaFuncAttributeMaxDynamicSharedMemorySize, smem_lay);

    const int* srcp = eidx;
    const int* dstp = eidx + Ee;
    const int GT = (Nn + 31) / 32;  // 313

    // Launch order: 4th kernel (ncu capture slot) is gemm_enc.
    fill_i32<<<(Nn + 255) / 256, 256>>>(pcnt, 0, Nn);                         // 1
    conv_a_kernel<<<(ROWP * 128 + 255) / 256, 256>>>(x, pximg);               // 2
    conv_w_kernel<<<dim3(48, 1), 256>>>(encW, pimg_enc, 128, 128, 0, 0);      // 3
    gemm_enc<<<GT, 256, smem_enc>>>(pximg, pimg_enc, encB, ph, pxh, Nn);      // 4 (captured)
    hist_kernel<<<(Ee + 255) / 256, 256>>>(dstp, pcnt);                       // 5
    scan_kernel<<<1, 1024>>>(pcnt, prow, ppos);                               // 6
    scat_ea_kernel<<<Ee / 8, 256>>>(srcp, dstp, ea, ppos, ppsrc, peah);       // 7
    conv_w_kernel<<<dim3(96, 4), 256>>>(W1, pimg_w1, 128, 256, 128 * 256, 6 * 256 * 72);
    conv_w_kernel<<<dim3(96, 4), 256>>>(W2, pimg_w2, 256, 128, 256 * 128, 12 * 128 * 72);

    for (int i = 0; i < Lh; i++) {
        agg_kernel<<<1250, 256>>>(pxh, peah, prow, ppsrc, tp, i, puimg);
        int nl = (i < Lh - 1) ? (i + 1) : 0;
        if (i == 0)
            gemm_layer<false><<<GT, 256, smem_lay>>>(
                puimg, pimg_w1 + (size_t)i * 6 * 256 * 72, pimg_w2 + (size_t)i * 12 * 128 * 72,
                b1 + (size_t)i * H2, mg + (size_t)i * H2, mb + (size_t)i * H2,
                b2 + (size_t)i * Hh, lg + (size_t)nl * Hh, lb + (size_t)nl * Hh,
                ph, pr, pxh, Nn);
        else
            gemm_layer<true><<<GT, 256, smem_lay>>>(
                puimg, pimg_w1 + (size_t)i * 6 * 256 * 72, pimg_w2 + (size_t)i * 12 * 128 * 72,
                b1 + (size_t)i * H2, mg + (size_t)i * H2, mb + (size_t)i * H2,
                b2 + (size_t)i * Hh, lg + (size_t)nl * Hh, lb + (size_t)nl * Hh,
                ph, pr, pxh, Nn);
    }

    // pr holds relu(LN(h; lg[0], lb[0])) fp32
    fill_f32<<<(NG * Hh + 255) / 256, 256>>>(ppool, 0.f, NG * Hh);
    pool_kernel<<<1250, 256>>>(pr, batch, ppool);
    final_kernel<<<36, 256>>>(ppool, linW, linB, out);
}

// round 16
// speedup vs baseline: 1.3302x; 1.3302x over previous
#include <cuda_runtime.h>
#include <cuda_fp16.h>
#include <cuda_bf16.h>
#include <math.h>
#include <stdint.h>

// Problem constants (fixed shapes)
#define Nn 10000
#define ROWP 10048          // Nn padded to 64
#define Ee 320000
#define Hh 128
#define H2 256
#define Lh 4
#define NG 64
#define NC 10
#define MSG_EPS 1e-7f

// ---------------- scratch (device globals; no allocation allowed) ----------------
__device__ float g_h[Nn * Hh];          // residual stream (fp32)
__device__ float g_r[Nn * Hh];          // relu(LN(h)) fp32 (pool input)
__device__ __half2 g_xh[Nn * 64];       // fp16 copy of agg input features
__device__ unsigned short g_ximg[ROWP * 256];    // x bf16 hi/lo image  (K=128)
__device__ unsigned short g_uimg[ROWP * 256];    // u bf16 hi/lo image  (K=128)
__device__ unsigned short g_hidimg[ROWP * 512];  // hid bf16 hi/lo image (K=256)
__device__ float g_pooled[NG * Hh];
__device__ int   g_cnt[Nn];
__device__ int   g_rowptr[Nn + 1];
__device__ int   g_pos[Nn];
__device__ int   g_psrc[Ee];
__device__ __half2 g_eah[(size_t)Ee * 64];       // edge_attr fp16, CSR order
// bf16-split weight images: NCH chunks of [COLS][72] halves (col-major, padded)
__device__ unsigned short g_img_enc[6 * 128 * 72];
__device__ unsigned short g_img_w1[4 * 6 * 256 * 72];
__device__ unsigned short g_img_w2[4 * 12 * 128 * 72];

static __device__ __forceinline__ unsigned pack_bf16x2(__nv_bfloat16 lo, __nv_bfloat16 hi) {
    unsigned short a = __bfloat16_as_ushort(lo);
    unsigned short b = __bfloat16_as_ushort(hi);
    return (unsigned)a | ((unsigned)b << 16);
}
static __device__ __forceinline__ unsigned h2u(__half2 v) {
    return *reinterpret_cast<unsigned*>(&v);
}
// split float4 into bf16 hi quad + lo quad, store as uint2 each
static __device__ __forceinline__ void store_hilo4(unsigned short* ph, unsigned short* pl,
                                                   float4 v) {
    __nv_bfloat16 h0 = __float2bfloat16_rn(v.x), h1 = __float2bfloat16_rn(v.y);
    __nv_bfloat16 h2 = __float2bfloat16_rn(v.z), h3 = __float2bfloat16_rn(v.w);
    __nv_bfloat16 l0 = __float2bfloat16_rn(v.x - __bfloat162float(h0));
    __nv_bfloat16 l1 = __float2bfloat16_rn(v.y - __bfloat162float(h1));
    __nv_bfloat16 l2 = __float2bfloat16_rn(v.z - __bfloat162float(h2));
    __nv_bfloat16 l3 = __float2bfloat16_rn(v.w - __bfloat162float(h3));
    *reinterpret_cast<uint2*>(ph) = make_uint2(pack_bf16x2(h0, h1), pack_bf16x2(h2, h3));
    *reinterpret_cast<uint2*>(pl) = make_uint2(pack_bf16x2(l0, l1), pack_bf16x2(l2, l3));
}
static __device__ __forceinline__ uint32_t smem_u32(const void* p) {
    uint32_t a;
    asm("{ .reg .u64 t; cvta.to.shared.u64 t, %1; cvt.u32.u64 %0, t; }" : "=r"(a) : "l"(p));
    return a;
}
static __device__ __forceinline__ void cp_async16(uint32_t sdst, const void* gsrc) {
    asm volatile("cp.async.cg.shared.global [%0], [%1], 16;" :: "r"(sdst), "l"(gsrc) : "memory");
}
static __device__ __forceinline__ void ldsm_x4(unsigned& a0, unsigned& a1, unsigned& a2,
                                               unsigned& a3, uint32_t addr) {
    asm volatile("ldmatrix.sync.aligned.m8n8.x4.shared.b16 {%0,%1,%2,%3}, [%4];"
                 : "=r"(a0), "=r"(a1), "=r"(a2), "=r"(a3) : "r"(addr));
}

// ---------------- prep: zero cnt + zero pooled + x -> bf16 hi/lo image ----------
__global__ void conv_a_kernel(const float* __restrict__ src, unsigned short* __restrict__ img,
                              int* __restrict__ cnt, float* __restrict__ pooled) {
    int idx = blockIdx.x * blockDim.x + threadIdx.x;
    if (idx < Nn) cnt[idx] = 0;
    if (idx < NG * Hh) pooled[idx] = 0.f;
    if (idx >= ROWP * 128) return;
    int row = idx >> 7, k = idx & 127;
    float v = (row < Nn) ? __ldg(&src[(size_t)row * 128 + k]) : 0.f;
    __nv_bfloat16 h = __float2bfloat16_rn(v);
    __nv_bfloat16 l = __float2bfloat16_rn(v - __bfloat162float(h));
    img[(size_t)row * 256 + k] = __bfloat16_as_ushort(h);
    img[(size_t)row * 256 + 128 + k] = __bfloat16_as_ushort(l);
}

// ---------------- CSR build ----------------
__global__ void hist_kernel(const int* __restrict__ dst, int* cnt) {
    int e = blockIdx.x * blockDim.x + threadIdx.x;
    if (e < Ee) atomicAdd(&cnt[dst[e]], 1);
}

__global__ __launch_bounds__(1024) void scan_kernel(const int* __restrict__ cnt,
                                                    int* rowptr, int* pos) {
    __shared__ int part[1024];
    const int CH = 10;
    int tid = threadIdx.x;
    int base = tid * CH;
    int loc[CH];
    int s = 0;
#pragma unroll
    for (int i = 0; i < CH; i++) {
        int idx = base + i;
        int v = (idx < Nn) ? cnt[idx] : 0;
        loc[i] = s;
        s += v;
    }
    part[tid] = s;
    __syncthreads();
    for (int off = 1; off < 1024; off <<= 1) {
        int v = (tid >= off) ? part[tid - off] : 0;
        __syncthreads();
        part[tid] += v;
        __syncthreads();
    }
    int pre = (tid > 0) ? part[tid - 1] : 0;
#pragma unroll
    for (int i = 0; i < CH; i++) {
        int idx = base + i;
        int v = pre + loc[i];
        if (idx <= Nn) rowptr[idx] = v;
        if (idx < Nn) pos[idx] = v;
    }
}

// fused scatter + edge_attr fp16 reorder (warp per edge)
__global__ void scat_ea_kernel(const int* __restrict__ src, const int* __restrict__ dst,
                               const float* __restrict__ ea, int* pos,
                               int* __restrict__ psrc, __half2* __restrict__ eah) {
    int j = (blockIdx.x * blockDim.x + threadIdx.x) >> 5;
    if (j >= Ee) return;
    int lane = threadIdx.x & 31;
    int slot = 0;
    if (lane == 0) {
        int d = __ldg(&dst[j]);
        slot = atomicAdd(&pos[d], 1);
        psrc[slot] = __ldg(&src[j]);
    }
    slot = __shfl_sync(0xffffffffu, slot, 0);
    float4 v = __ldg(reinterpret_cast<const float4*>(ea + (size_t)j * Hh) + lane);
    eah[(size_t)slot * 64 + lane * 2]     = __floats2half2_rn(v.x, v.y);
    eah[(size_t)slot * 64 + lane * 2 + 1] = __floats2half2_rn(v.z, v.w);
}

// ---------------- weight image prep ----------------
__global__ void conv_w_kernel(const float* __restrict__ Wsrc, unsigned short* __restrict__ img,
                              int K, int COLS, int lstride, int imgstride) {
    int layer = blockIdx.y;
    const float* W = Wsrc + (size_t)layer * lstride;
    unsigned short* out = img + (size_t)layer * imgstride;
    int total = (3 * K / 64) * COLS * 64;
    for (int idx = blockIdx.x * blockDim.x + threadIdx.x; idx < total;
         idx += gridDim.x * blockDim.x) {
        int c = idx / (COLS * 64);
        int rem = idx % (COLS * 64);
        int n = rem / 64, kc = rem % 64;
        int kp = c * 64 + kc;
        int sec_lo = (kp >= K && kp < 2 * K);
        int kg = kp;
        if (kg >= 2 * K) kg -= 2 * K;
        else if (kg >= K) kg -= K;
        float w = __ldg(&W[(size_t)kg * COLS + n]);
        __nv_bfloat16 h = __float2bfloat16_rn(w);
        if (sec_lo) h = __float2bfloat16_rn(w - __bfloat162float(h));
        out[(size_t)c * COLS * 72 + n * 72 + kc] = __bfloat16_as_ushort(h);
    }
}

// ---------------- aggregation (fp16 x, writes u bf16 hi/lo image) ----------------
__global__ void agg_kernel(const __half2* __restrict__ xh, const __half2* __restrict__ eah,
                           const int* __restrict__ rowptr, const int* __restrict__ psrc,
                           const float* __restrict__ tp, int layer,
                           unsigned short* __restrict__ uimg) {
    int w = (blockIdx.x * blockDim.x + threadIdx.x) >> 5;
    if (w >= Nn) return;
    int lane = threadIdx.x & 31;
    float t = tp[layer];
    int beg = rowptr[w], end = rowptr[w + 1];
    float Sx = 0.f, Sy = 0.f, Sz = 0.f, Sw = 0.f;
    float Ax = 0.f, Ay = 0.f, Az = 0.f, Aw = 0.f;
#pragma unroll 4
    for (int j = beg; j < end; j++) {
        int s = __ldg(&psrc[j]);
        uint2 eu = __ldg(reinterpret_cast<const uint2*>(eah + (size_t)j * 64) + lane);
        uint2 xu = __ldg(reinterpret_cast<const uint2*>(xh + (size_t)s * 64) + lane);
        float2 e01 = __half22float2(*reinterpret_cast<__half2*>(&eu.x));
        float2 e23 = __half22float2(*reinterpret_cast<__half2*>(&eu.y));
        float2 x01 = __half22float2(*reinterpret_cast<__half2*>(&xu.x));
        float2 x23 = __half22float2(*reinterpret_cast<__half2*>(&xu.y));
        float mx = fmaxf(x01.x + e01.x, 0.f) + MSG_EPS;
        float my = fmaxf(x01.y + e01.y, 0.f) + MSG_EPS;
        float mz = fmaxf(x23.x + e23.x, 0.f) + MSG_EPS;
        float mw = fmaxf(x23.y + e23.y, 0.f) + MSG_EPS;
        float exx = __expf(mx * t), exy = __expf(my * t);
        float exz = __expf(mz * t), exw = __expf(mw * t);
        Sx += exx; Sy += exy; Sz += exz; Sw += exw;
        Ax = fmaf(mx, exx, Ax); Ay = fmaf(my, exy, Ay);
        Az = fmaf(mz, exz, Az); Aw = fmaf(mw, exw, Aw);
    }
    uint2 xnu = *(reinterpret_cast<const uint2*>(xh + (size_t)w * 64) + lane);
    float2 xn01 = __half22float2(*reinterpret_cast<__half2*>(&xnu.x));
    float2 xn23 = __half22float2(*reinterpret_cast<__half2*>(&xnu.y));
    float4 o;
    if (end > beg) {
        o.x = Ax / Sx + xn01.x;
        o.y = Ay / Sy + xn01.y;
        o.z = Az / Sz + xn23.x;
        o.w = Aw / Sw + xn23.y;
    } else {
        o = make_float4(xn01.x, xn01.y, xn23.x, xn23.y);
    }
    unsigned short* bh = uimg + (size_t)w * 256 + lane * 4;
    store_hilo4(bh, bh + 128, o);
}

// ================= mma.sync bf16-split GEMM (32-row tiles, 2-3 CTAs/SM) =====
// CTA: 32 rows x COLS, 256 threads, grid 313. warps 2m x 4n; warp tile 16 x COLS/4.
// EPI 0: C = D + bias (fp32), Yh = fp16 copy
// EPI 1: ImgOut = bf16 hi/lo of relu(LN(D + bias)) over COLS=256
// EPI 2: h = D + bias (+C if ACC); C = h; y = relu(LN(h)); Yf fp32; Yh fp16
template <int K, int COLS, int EPI, bool ACC>
__global__ __launch_bounds__(256, 3) void gemm_mma(const unsigned short* __restrict__ Aimg,
                                                   const unsigned short* __restrict__ img,
                                                   const float* __restrict__ bias,
                                                   const float* __restrict__ lng,
                                                   const float* __restrict__ lnb,
                                                   float* __restrict__ C,
                                                   float* __restrict__ Yf,
                                                   __half2* __restrict__ Yh,
                                                   unsigned short* __restrict__ ImgOut,
                                                   int nrows) {
    constexpr int SA = K + 8;
    constexpr int NCH = 3 * K / 64;
    constexpr int WB = COLS * 72;
    constexpr int NT = COLS / 32;
    constexpr int CS = COLS + 4;
    constexpr int CPR = K / 8;

    extern __shared__ __align__(16) unsigned short smem_us[];
    unsigned short* sAhi = smem_us;
    unsigned short* sAlo = smem_us + 32 * SA;
    unsigned short* sW = smem_us + 64 * SA;
    float* Cbuf = reinterpret_cast<float*>(smem_us);

    int tid = threadIdx.x, wid = tid >> 5, lane = tid & 31;
    int g = lane >> 2, tg = lane & 3;
    int wm = wid & 1, wn = wid >> 1;
    int row0 = blockIdx.x * 32;
    uint32_t sWU = smem_u32(sW);
    uint32_t aU_hi = smem_u32(sAhi);
    uint32_t aU_lo = smem_u32(sAlo);

    // ---- A copy via cp.async (image already bf16 hi/lo) ----
    {
        const char* base = reinterpret_cast<const char*>(Aimg) + (size_t)row0 * 4 * K;
        for (int i = tid; i < 64 * CPR; i += 256) {
            int piece = i / CPR, off = i % CPR;
            int r = piece >> 1, hl = piece & 1;
            uint32_t dst = (hl ? aU_lo : aU_hi) + (uint32_t)(r * SA * 2 + off * 16);
            cp_async16(dst, base + (size_t)r * 4 * K + hl * 2 * K + off * 16);
        }
    }
    // ---- prefetch W chunk 0 ----
    {
        const char* srcb = reinterpret_cast<const char*>(img);
        for (int i = tid; i < COLS * 9; i += 256)
            cp_async16(sWU + (uint32_t)i * 16, srcb + (size_t)i * 16);
        asm volatile("cp.async.commit_group;" ::: "memory");
    }

    float acc[NT][4];
#pragma unroll
    for (int j = 0; j < NT; j++)
#pragma unroll
        for (int q = 0; q < 4; q++) acc[j][q] = 0.f;

    int rowA = wm * 16 + (lane & 15);
    int colsel = (lane >> 4) << 3;

    for (int c = 0; c < NCH; c++) {
        asm volatile("cp.async.wait_group 0;" ::: "memory");
        __syncthreads();
        if (c + 1 < NCH) {
            uint32_t dstb = sWU + (uint32_t)(((c + 1) & 1) * WB * 2);
            const char* srcb = reinterpret_cast<const char*>(img) + (size_t)(c + 1) * WB * 2;
            for (int i = tid; i < COLS * 9; i += 256)
                cp_async16(dstb + (uint32_t)i * 16, srcb + (size_t)i * 16);
            asm volatile("cp.async.commit_group;" ::: "memory");
        }
        int kp = c * 64;
        uint32_t aU = (kp < 2 * K) ? aU_hi : aU_lo;
        int koffA = kp;
        if (koffA >= 2 * K) koffA -= 2 * K;
        else if (koffA >= K) koffA -= K;
        const unsigned short* sWb = sW + (c & 1) * WB;
#pragma unroll
        for (int ks = 0; ks < 4; ks++) {
            int kw = ks * 16 + tg * 2;
            unsigned bf0[NT], bf1[NT];
#pragma unroll
            for (int j = 0; j < NT; j++) {
                int n = wn * (COLS / 4) + j * 8 + g;
                bf0[j] = *reinterpret_cast<const unsigned*>(sWb + n * 72 + kw);
                bf1[j] = *reinterpret_cast<const unsigned*>(sWb + n * 72 + kw + 8);
            }
            unsigned a0, a1, a2, a3;
            ldsm_x4(a0, a1, a2, a3,
                    aU + (uint32_t)((rowA * SA + koffA + ks * 16 + colsel) * 2));
#pragma unroll
            for (int j = 0; j < NT; j++) {
                asm volatile(
                    "mma.sync.aligned.m16n8k16.row.col.f32.bf16.bf16.f32 "
                    "{%0,%1,%2,%3}, {%4,%5,%6,%7}, {%8,%9}, {%0,%1,%2,%3};"
                    : "+f"(acc[j][0]), "+f"(acc[j][1]), "+f"(acc[j][2]), "+f"(acc[j][3])
                    : "r"(a0), "r"(a1), "r"(a2), "r"(a3), "r"(bf0[j]), "r"(bf1[j]));
            }
        }
        __syncthreads();
    }

    // ---- acc -> smem (repurposed) ----
    {
        int r = wm * 16 + g;
#pragma unroll
        for (int j = 0; j < NT; j++) {
            int ncol = wn * (COLS / 4) + j * 8 + tg * 2;
            *reinterpret_cast<float2*>(Cbuf + r * CS + ncol) = make_float2(acc[j][0], acc[j][1]);
            *reinterpret_cast<float2*>(Cbuf + (r + 8) * CS + ncol) =
                make_float2(acc[j][2], acc[j][3]);
        }
    }
    __syncthreads();

    // ---- epilogue: warp handles 4 rows ----
    if (EPI == 0 || EPI == 2) {
        float4 b4 = __ldg(reinterpret_cast<const float4*>(bias) + lane);
        float4 gv, bv;
        if (EPI == 2) {
            gv = __ldg(reinterpret_cast<const float4*>(lng) + lane);
            bv = __ldg(reinterpret_cast<const float4*>(lnb) + lane);
        }
        for (int rr = 0; rr < 4; rr++) {
            int r = wid * 4 + rr;
            int row = row0 + r;
            if (row >= nrows) break;
            float4 h = reinterpret_cast<const float4*>(Cbuf + r * CS)[lane];
            h.x += b4.x; h.y += b4.y; h.z += b4.z; h.w += b4.w;
            if (EPI == 0) {
                reinterpret_cast<float4*>(C + (size_t)row * 128)[lane] = h;
                reinterpret_cast<uint2*>(Yh + (size_t)row * 64)[lane] = make_uint2(
                    h2u(__floats2half2_rn(h.x, h.y)), h2u(__floats2half2_rn(h.z, h.w)));
                continue;
            }
            if (ACC) {
                float4 old = __ldg(reinterpret_cast<const float4*>(C + (size_t)row * 128) + lane);
                h.x += old.x; h.y += old.y; h.z += old.z; h.w += old.w;
            }
            float s = h.x + h.y + h.z + h.w;
            float s2 = h.x * h.x + h.y * h.y + h.z * h.z + h.w * h.w;
#pragma unroll
            for (int o = 16; o > 0; o >>= 1) {
                s += __shfl_xor_sync(0xffffffffu, s, o);
                s2 += __shfl_xor_sync(0xffffffffu, s2, o);
            }
            float mu = s * (1.f / 128.f);
            float var = s2 * (1.f / 128.f) - mu * mu;
            float inv = rsqrtf(var + 1e-5f);
            float4 y;
            y.x = fmaxf((h.x - mu) * inv * gv.x + bv.x, 0.f);
            y.y = fmaxf((h.y - mu) * inv * gv.y + bv.y, 0.f);
            y.z = fmaxf((h.z - mu) * inv * gv.z + bv.z, 0.f);
            y.w = fmaxf((h.w - mu) * inv * gv.w + bv.w, 0.f);
            reinterpret_cast<float4*>(C + (size_t)row * 128)[lane] = h;
            reinterpret_cast<float4*>(Yf + (size_t)row * 128)[lane] = y;
            reinterpret_cast<uint2*>(Yh + (size_t)row * 64)[lane] = make_uint2(
                h2u(__floats2half2_rn(y.x, y.y)), h2u(__floats2half2_rn(y.z, y.w)));
        }
    } else {  // EPI == 1, COLS = 256 -> bf16 hi/lo image out
        float4 b4a = __ldg(reinterpret_cast<const float4*>(bias) + lane);
        float4 b4b = __ldg(reinterpret_cast<const float4*>(bias) + 32 + lane);
        float4 gva = __ldg(reinterpret_cast<const float4*>(lng) + lane);
        float4 gvb = __ldg(reinterpret_cast<const float4*>(lng) + 32 + lane);
        float4 bva = __ldg(reinterpret_cast<const float4*>(lnb) + lane);
        float4 bvb = __ldg(reinterpret_cast<const float4*>(lnb) + 32 + lane);
        for (int rr = 0; rr < 4; rr++) {
            int r = wid * 4 + rr;
            int row = row0 + r;
            if (row >= nrows) break;
            float4 va = reinterpret_cast<const float4*>(Cbuf + r * CS)[lane];
            float4 vb = *reinterpret_cast<const float4*>(Cbuf + r * CS + 128 + lane * 4);
            va.x += b4a.x; va.y += b4a.y; va.z += b4a.z; va.w += b4a.w;
            vb.x += b4b.x; vb.y += b4b.y; vb.z += b4b.z; vb.w += b4b.w;
            float s = va.x + va.y + va.z + va.w + vb.x + vb.y + vb.z + vb.w;
            float s2 = va.x * va.x + va.y * va.y + va.z * va.z + va.w * va.w +
                       vb.x * vb.x + vb.y * vb.y + vb.z * vb.z + vb.w * vb.w;
#pragma unroll
            for (int o = 16; o > 0; o >>= 1) {
                s += __shfl_xor_sync(0xffffffffu, s, o);
                s2 += __shfl_xor_sync(0xffffffffu, s2, o);
            }
            float mu = s * (1.f / 256.f);
            float var = s2 * (1.f / 256.f) - mu * mu;
            float inv = rsqrtf(var + 1e-5f);
            float4 ya, yb;
            ya.x = fmaxf((va.x - mu) * inv * gva.x + bva.x, 0.f);
            ya.y = fmaxf((va.y - mu) * inv * gva.y + bva.y, 0.f);
            ya.z = fmaxf((va.z - mu) * inv * gva.z + bva.z, 0.f);
            ya.w = fmaxf((va.w - mu) * inv * gva.w + bva.w, 0.f);
            yb.x = fmaxf((vb.x - mu) * inv * gvb.x + bvb.x, 0.f);
            yb.y = fmaxf((vb.y - mu) * inv * gvb.y + bvb.y, 0.f);
            yb.z = fmaxf((vb.z - mu) * inv * gvb.z + bvb.z, 0.f);
            yb.w = fmaxf((vb.w - mu) * inv * gvb.w + bvb.w, 0.f);
            unsigned short* rowp = ImgOut + (size_t)row * 512;
            store_hilo4(rowp + lane * 4, rowp + 256 + lane * 4, ya);
            store_hilo4(rowp + 128 + lane * 4, rowp + 256 + 128 + lane * 4, yb);
        }
    }
}

// ---------------- global_add_pool ----------------
__global__ void pool_kernel(const float* __restrict__ r, const int* __restrict__ batch,
                            float* pooled) {
    int w = (blockIdx.x * blockDim.x + threadIdx.x) >> 5;
    if (w >= Nn) return;
    int lane = threadIdx.x & 31;
    int gidx = batch[w];
    float4 v = *(reinterpret_cast<const float4*>(r + (size_t)w * Hh) + lane);
    float* dp = pooled + gidx * Hh + lane * 4;
    atomicAdd(dp + 0, v.x);
    atomicAdd(dp + 1, v.y);
    atomicAdd(dp + 2, v.z);
    atomicAdd(dp + 3, v.w);
}

// ---------------- classifier + output assembly ----------------
__global__ void final_kernel(const float* __restrict__ pooled, const float* __restrict__ linW,
                             const float* __restrict__ linb, float* __restrict__ out) {
    int idx = blockIdx.x * blockDim.x + threadIdx.x;
    int total = blockDim.x * gridDim.x;
    if (idx < NG * NC) {
        int gi = idx / NC, c = idx % NC;
        float sum = linb[c];
#pragma unroll 8
        for (int k = 0; k < Hh; k++) sum = fmaf(pooled[gi * Hh + k], linW[k * NC + c], sum);
        out[idx] = sum;
    }
    for (int i = idx; i < NG * Hh; i += total) out[NG * NC + i] = pooled[i];
}

// ---------------- launch ----------------
extern "C" void kernel_launch(void* const* d_in, const int* in_sizes, int n_in,
                              void* d_out, int out_size) {
    const float* x    = (const float*)d_in[0];
    const float* ea   = (const float*)d_in[1];
    const float* encW = (const float*)d_in[2];
    const float* encB = (const float*)d_in[3];
    const float* tp   = (const float*)d_in[4];
    const float* W1   = (const float*)d_in[5];
    const float* b1   = (const float*)d_in[6];
    const float* mg   = (const float*)d_in[7];
    const float* mb   = (const float*)d_in[8];
    const float* W2   = (const float*)d_in[9];
    const float* b2   = (const float*)d_in[10];
    const float* lg   = (const float*)d_in[11];
    const float* lb   = (const float*)d_in[12];
    const float* linW = (const float*)d_in[13];
    const float* linB = (const float*)d_in[14];
    const int*   eidx = (const int*)d_in[15];
    const int*   batch= (const int*)d_in[16];
    float* out = (float*)d_out;

    float *ph, *pr, *ppool;
    int *pcnt, *prow, *ppos, *ppsrc;
    __half2 *peah, *pxh;
    unsigned short *pimg_enc, *pimg_w1, *pimg_w2, *pximg, *puimg, *phidimg;
    cudaGetSymbolAddress((void**)&ph, g_h);
    cudaGetSymbolAddress((void**)&pr, g_r);
    cudaGetSymbolAddress((void**)&pxh, g_xh);
    cudaGetSymbolAddress((void**)&pximg, g_ximg);
    cudaGetSymbolAddress((void**)&puimg, g_uimg);
    cudaGetSymbolAddress((void**)&phidimg, g_hidimg);
    cudaGetSymbolAddress((void**)&ppool, g_pooled);
    cudaGetSymbolAddress((void**)&pcnt, g_cnt);
    cudaGetSymbolAddress((void**)&prow, g_rowptr);
    cudaGetSymbolAddress((void**)&ppos, g_pos);
    cudaGetSymbolAddress((void**)&ppsrc, g_psrc);
    cudaGetSymbolAddress((void**)&peah, g_eah);
    cudaGetSymbolAddress((void**)&pimg_enc, g_img_enc);
    cudaGetSymbolAddress((void**)&pimg_w1, g_img_w1);
    cudaGetSymbolAddress((void**)&pimg_w2, g_img_w2);

    // smem bytes: 64*(K+8)*2 + 2*COLS*72*2
    const int smem_enc = (64 * 136 + 2 * 128 * 72) * 2;   // 54272
    const int smem_g1  = (64 * 136 + 2 * 256 * 72) * 2;   // 91136
    const int smem_g2  = (64 * 264 + 2 * 128 * 72) * 2;   // 70656
    cudaFuncSetAttribute((const void*)gemm_mma<128, 128, 0, false>,
                         cudaFuncAttributeMaxDynamicSharedMemorySize, smem_enc);
    cudaFuncSetAttribute((const void*)gemm_mma<128, 256, 1, false>,
                         cudaFuncAttributeMaxDynamicSharedMemorySize, smem_g1);
    cudaFuncSetAttribute((const void*)gemm_mma<256, 128, 2, false>,
                         cudaFuncAttributeMaxDynamicSharedMemorySize, smem_g2);
    cudaFuncSetAttribute((const void*)gemm_mma<256, 128, 2, true>,
                         cudaFuncAttributeMaxDynamicSharedMemorySize, smem_g2);

    const int* srcp = eidx;
    const int* dstp = eidx + Ee;
    const int GT = (Nn + 31) / 32;  // 313

    // Launch order: 4th kernel (ncu capture slot) is gemm_mma (enc).
    conv_a_kernel<<<(ROWP * 128 + 255) / 256, 256>>>(x, pximg, pcnt, ppool);  // 1 (+fills)
    conv_w_kernel<<<dim3(48, 1), 256>>>(encW, pimg_enc, 128, 128, 0, 0);      // 2
    hist_kernel<<<(Ee + 255) / 256, 256>>>(dstp, pcnt);                       // 3
    gemm_mma<128, 128, 0, false><<<GT, 256, smem_enc>>>(                      // 4 (captured)
        pximg, pimg_enc, encB, nullptr, nullptr, ph, nullptr, pxh, nullptr, Nn);
    scan_kernel<<<1, 1024>>>(pcnt, prow, ppos);                               // 5
    scat_ea_kernel<<<Ee / 8, 256>>>(srcp, dstp, ea, ppos, ppsrc, peah);       // 6
    conv_w_kernel<<<dim3(96, 4), 256>>>(W1, pimg_w1, 128, 256, 128 * 256, 6 * 256 * 72);
    conv_w_kernel<<<dim3(96, 4), 256>>>(W2, pimg_w2, 256, 128, 256 * 128, 12 * 128 * 72);

    for (int i = 0; i < Lh; i++) {
        agg_kernel<<<1250, 256>>>(pxh, peah, prow, ppsrc, tp, i, puimg);
        // hid_img = bf16(relu(LN(u @ W1 + b1)))
        gemm_mma<128, 256, 1, false><<<GT, 256, smem_g1>>>(
            puimg, pimg_w1 + (size_t)i * 6 * 256 * 72, b1 + (size_t)i * H2,
            mg + (size_t)i * H2, mb + (size_t)i * H2, nullptr, nullptr, nullptr, phidimg, Nn);
        // h (+)= hid @ W2 + b2 ; y = relu(LN(h; next params)) -> pr (fp32) + xh (fp16)
        int nl = (i < Lh - 1) ? (i + 1) : 0;
        if (i == 0)
            gemm_mma<256, 128, 2, false><<<GT, 256, smem_g2>>>(
                phidimg, pimg_w2 + (size_t)i * 12 * 128 * 72, b2 + (size_t)i * Hh,
                lg + (size_t)nl * Hh, lb + (size_t)nl * Hh, ph, pr, pxh, nullptr, Nn);
        else
            gemm_mma<256, 128, 2, true><<<GT, 256, smem_g2>>>(
                phidimg, pimg_w2 + (size_t)i * 12 * 128 * 72, b2 + (size_t)i * Hh,
                lg + (size_t)nl * Hh, lb + (size_t)nl * Hh, ph, pr, pxh, nullptr, Nn);
    }

    // pr holds relu(LN(h; lg[0], lb[0])) fp32
    pool_kernel<<<1250, 256>>>(pr, batch, ppool);
    final_kernel<<<36, 256>>>(ppool, linW, linB, out);
}